// round 4
// baseline (speedup 1.0000x reference)
#include <cuda_runtime.h>

#define TSEQ 512
#define INF  14
#define HID  8

typedef unsigned long long ull;

__device__ __forceinline__ ull pk(float lo, float hi){
    ull r; asm("mov.b64 %0, {%1,%2};" : "=l"(r) : "f"(lo), "f"(hi)); return r;
}
__device__ __forceinline__ float2 upk(ull v){
    float2 r; asm("mov.b64 {%0,%1}, %2;" : "=f"(r.x), "=f"(r.y) : "l"(v)); return r;
}
__device__ __forceinline__ ull ffma2(ull a, ull b, ull c){
    ull d; asm("fma.rn.f32x2 %0, %1, %2, %3;" : "=l"(d) : "l"(a), "l"(b), "l"(c)); return d;
}
__device__ __forceinline__ float tanhx(float x){
    float r; asm("tanh.approx.f32 %0, %1;" : "=f"(r) : "f"(x)); return r;
}
__device__ __forceinline__ float sigx(float x){
    return fmaf(0.5f, tanhx(0.5f * x), 0.5f);
}

// 2 batch elements per warp; element = 16 lanes.
// lane layout within element: l = p*8 + j  (p in {0,1}, j in 0..7)
//   p=0 lane computes gate rows i(j)=j     and f(j)=8+j
//   p=1 lane computes gate rows g(j)=16+j  and o(j)=24+j
// After activations, one shfl.xor(8) exchange gives every lane all 4 gates;
// h and c are computed redundantly in both halves.
__global__ __launch_bounds__(32, 14) void lstm_forex_kernel(
    const float* __restrict__ x,
    const float* __restrict__ Wih1, const float* __restrict__ Whh1,
    const float* __restrict__ bih1, const float* __restrict__ bhh1,
    const float* __restrict__ Wih2, const float* __restrict__ Whh2,
    const float* __restrict__ bih2, const float* __restrict__ bhh2,
    const float* __restrict__ bn_gamma, const float* __restrict__ bn_beta,
    const float* __restrict__ bn_mean, const float* __restrict__ bn_var,
    const float* __restrict__ w1, const float* __restrict__ b1,
    const float* __restrict__ w2, const float* __restrict__ b2,
    float* __restrict__ out, int Bn)
{
    const int lane  = threadIdx.x & 31;
    const int j     = lane & 7;
    const int p     = (lane >> 3) & 1;        // gate-pair half
    const int gbase = lane & 16;               // element group base lane
    const int e     = blockIdx.x * 2 + (lane >> 4);
    const bool valid = (e < Bn);
    const int ec = valid ? e : (Bn > 0 ? Bn - 1 : 0);
    const unsigned FULL = 0xffffffffu;

    const int r0 = p * 16 + j;                 // i (p=0) / g (p=1)
    const int r1 = p * 16 + 8 + j;             // f (p=0) / o (p=1)

    // activation constants for a0: p=0 sigmoid, p=1 tanh
    const float sa = p ? 1.0f : 0.5f;
    const float ca = p ? 1.0f : 0.5f;
    const float cb = p ? 0.0f : 0.5f;

    // ---- packed per-lane weights (2 rows) ----
    ull wx0[7], wx1[7];        // Wih1 rows r0, r1: (w[2k], w[2k+1])
    ull wh0[4], wh1_[4];       // Whh1 rows
    ull wl0[8], wl1[8];        // layer2 interleaved: (Wih2[r][k], Whh2[r][k])
#pragma unroll
    for (int k = 0; k < 7; k++){
        wx0[k] = pk(Wih1[r0 * 14 + 2*k], Wih1[r0 * 14 + 2*k + 1]);
        wx1[k] = pk(Wih1[r1 * 14 + 2*k], Wih1[r1 * 14 + 2*k + 1]);
    }
#pragma unroll
    for (int k = 0; k < 4; k++){
        wh0[k]  = pk(Whh1[r0 * 8 + 2*k], Whh1[r0 * 8 + 2*k + 1]);
        wh1_[k] = pk(Whh1[r1 * 8 + 2*k], Whh1[r1 * 8 + 2*k + 1]);
    }
#pragma unroll
    for (int k = 0; k < 8; k++){
        wl0[k] = pk(Wih2[r0 * 8 + k], Whh2[r0 * 8 + k]);
        wl1[k] = pk(Wih2[r1 * 8 + k], Whh2[r1 * 8 + k]);
    }
    const ull pb1r0 = pk(bih1[r0] + bhh1[r0], 0.f);
    const ull pb1r1 = pk(bih1[r1] + bhh1[r1], 0.f);
    const ull pb2r0 = pk(bih2[r0] + bhh2[r0], 0.f);
    const ull pb2r1 = pk(bih2[r1] + bhh2[r1], 0.f);

    // x[e, t, :]: 14 floats = 7 packed pairs
    const ull* px = reinterpret_cast<const ull*>(x) + (size_t)ec * (TSEQ * INF / 2);
    ull xb[7];
#pragma unroll
    for (int k = 0; k < 7; k++) xb[k] = px[k];
    px += 7;

    float h1 = 0.f, c1 = 0.f, h2 = 0.f, c2 = 0.f;

#pragma unroll 1
    for (int t = 0; t < TSEQ; t++){
        // ---------------- layer 1 ----------------
        ull a0 = pb1r0, a1 = pb1r1;
#pragma unroll
        for (int k = 0; k < 7; k++){
            a0 = ffma2(wx0[k], xb[k], a0);
            a1 = ffma2(wx1[k], xb[k], a1);
        }
        if (t + 1 < TSEQ){                    // prefetch next timestep's x
#pragma unroll
            for (int k = 0; k < 7; k++) xb[k] = px[k];
            px += 7;
        }
#pragma unroll
        for (int k = 0; k < 4; k++){
            const float ha = __shfl_sync(FULL, h1, gbase + 2*k);
            const float hb = __shfl_sync(FULL, h1, gbase + 2*k + 1);
            const ull hp = pk(ha, hb);
            a0 = ffma2(wh0[k],  hp, a0);
            a1 = ffma2(wh1_[k], hp, a1);
        }
        {
            const float2 u0 = upk(a0), u1 = upk(a1);
            const float g0 = fmaf(ca, tanhx(sa * (u0.x + u0.y)), cb); // i or g
            const float g1 = sigx(u1.x + u1.y);                       // f or o
            const float e0 = __shfl_xor_sync(FULL, g0, 8);
            const float e1 = __shfl_xor_sync(FULL, g1, 8);
            const float iv = p ? e0 : g0;
            const float gv = p ? g0 : e0;
            const float fv = p ? e1 : g1;
            const float ov = p ? g1 : e1;
            c1 = fmaf(fv, c1, iv * gv);
            h1 = ov * tanhx(c1);
        }
        // ---------------- layer 2 ----------------
        a0 = pb2r0; a1 = pb2r1;
#pragma unroll
        for (int k = 0; k < 8; k++){
            const float h1k = __shfl_sync(FULL, h1, gbase + k);
            const float h2k = __shfl_sync(FULL, h2, gbase + k);
            const ull hp = pk(h1k, h2k);
            a0 = ffma2(wl0[k], hp, a0);
            a1 = ffma2(wl1[k], hp, a1);
        }
        {
            const float2 u0 = upk(a0), u1 = upk(a1);
            const float g0 = fmaf(ca, tanhx(sa * (u0.x + u0.y)), cb);
            const float g1 = sigx(u1.x + u1.y);
            const float e0 = __shfl_xor_sync(FULL, g0, 8);
            const float e1 = __shfl_xor_sync(FULL, g1, 8);
            const float iv = p ? e0 : g0;
            const float gv = p ? g0 : e0;
            const float fv = p ? e1 : g1;
            const float ov = p ? g1 : e1;
            c2 = fmaf(fv, c2, iv * gv);
            h2 = ov * tanhx(c2);
        }
    }

    // ---------------- epilogue: BatchNorm (eval) + MLP head ----------------
    const float scale = bn_gamma[j] * rsqrtf(bn_var[j] + 1e-5f);
    const float nrm   = fmaf(h2 - bn_mean[j], scale, bn_beta[j]);

    float p0 = w1[0 * 8 + j] * nrm;
    float p1 = w1[1 * 8 + j] * nrm;
    float p2 = w1[2 * 8 + j] * nrm;
    float p3 = w1[3 * 8 + j] * nrm;
#pragma unroll
    for (int off = 4; off > 0; off >>= 1){
        p0 += __shfl_xor_sync(FULL, p0, off);
        p1 += __shfl_xor_sync(FULL, p1, off);
        p2 += __shfl_xor_sync(FULL, p2, off);
        p3 += __shfl_xor_sync(FULL, p3, off);
    }
    if (valid && (lane & 15) == 0){
        float o = b2[0];
        o = fmaf(w2[0], fmaxf(p0 + b1[0], 0.f), o);
        o = fmaf(w2[1], fmaxf(p1 + b1[1], 0.f), o);
        o = fmaf(w2[2], fmaxf(p2 + b1[2], 0.f), o);
        o = fmaf(w2[3], fmaxf(p3 + b1[3], 0.f), o);
        out[e] = o;
    }
}

extern "C" void kernel_launch(void* const* d_in, const int* in_sizes, int n_in,
                              void* d_out, int out_size)
{
    const float* x        = (const float*)d_in[0];
    const float* Wih1     = (const float*)d_in[1];
    const float* Whh1     = (const float*)d_in[2];
    const float* bih1     = (const float*)d_in[3];
    const float* bhh1     = (const float*)d_in[4];
    const float* Wih2     = (const float*)d_in[5];
    const float* Whh2     = (const float*)d_in[6];
    const float* bih2     = (const float*)d_in[7];
    const float* bhh2     = (const float*)d_in[8];
    const float* bn_gamma = (const float*)d_in[9];
    const float* bn_beta  = (const float*)d_in[10];
    const float* bn_mean  = (const float*)d_in[11];
    const float* bn_var   = (const float*)d_in[12];
    const float* w1       = (const float*)d_in[13];
    const float* b1       = (const float*)d_in[14];
    const float* w2       = (const float*)d_in[15];
    const float* b2       = (const float*)d_in[16];

    const int Bn = in_sizes[0] / (TSEQ * INF);
    const int grid = (Bn + 1) / 2;            // 2 batch elements per warp, 1 warp/block

    lstm_forex_kernel<<<grid, 32>>>(x, Wih1, Whh1, bih1, bhh1,
                                    Wih2, Whh2, bih2, bhh2,
                                    bn_gamma, bn_beta, bn_mean, bn_var,
                                    w1, b1, w2, b2,
                                    (float*)d_out, Bn);
}